// round 3
// baseline (speedup 1.0000x reference)
#include <cuda_runtime.h>
#include <cuda_bf16.h>
#include <math.h>

// ---------------- problem constants ----------------
#define NN      100000
#define EE      1600000
#define HH      64
#define FINW    16
#define LL      3
#define KLUT    1024
#define CUT     5.0f
#define BN_INV  0.9995003749f   // 1/sqrt(1+1e-3)
#define EMB_BLOCKS 25000        // 25000*256 == NN*HH
#define LUT_BLOCKS 16

typedef unsigned long long u64;

// ---------------- device scratch ----------------
__device__ float4 g_h[NN * 16];                       // fp32 master h [N,64]
__device__ __align__(16) __nv_bfloat16 g_hb[NN * 64]; // bf16 gather copy
__device__ float4 g_agg[NN * 16];
__device__ float4 g_csr[EE];                          // {col, fs0, fs1, fs2}
__device__ int    g_deg[NN];
__device__ int    g_rowstart[NN];
__device__ int    g_cursor[NN];
__device__ int    g_bsums[128];
__device__ float  g_lut[LL * (KLUT + 1)];
__device__ float  g_gsum[HH];

__device__ __forceinline__ float sp(float x) {
    return fmaxf(x, 0.f) + log1pf(__expf(-fabsf(x)));
}
__device__ __forceinline__ u64 dup2(float x) {
    u64 r; asm("mov.b64 %0, {%1, %1};" : "=l"(r) : "f"(x)); return r;
}
__device__ __forceinline__ void fma2(u64 &a, u64 x, u64 w) {
    asm("fma.rn.f32x2 %0, %1, %2, %0;" : "+l"(a) : "l"(x), "l"(w));
}
__device__ __forceinline__ float2 unpk(u64 a) {
    float2 r; asm("mov.b64 {%0, %1}, %2;" : "=f"(r.x), "=f"(r.y) : "l"(a)); return r;
}

// ---------------- setup: embed + deg/gsum zero + filter-LUT ----------------
__global__ void k_setup(const float* __restrict__ x,
                        const float* __restrict__ W,
                        const float* __restrict__ b,
                        const float* __restrict__ fW1,
                        const float* __restrict__ fb1,
                        const float* __restrict__ fW2,
                        const float* __restrict__ fb2) {
    __shared__ float w2s[LL * HH];
    __shared__ float b2s[LL];
    int bidx = blockIdx.x, t = threadIdx.x;
    if (bidx < EMB_BLOCKS) {
        if (t < 4) g_deg[bidx * 4 + t] = 0;
        int idx = bidx * 256 + t;
        int n = idx >> 6, j = idx & 63;
        float acc = b[j];
        const float* xr = x + n * FINW;
#pragma unroll
        for (int k = 0; k < FINW; k++) acc += xr[k] * W[k * HH + j];
        ((float*)g_h)[idx] = acc;
        g_hb[idx] = __float2bfloat16_rn(acc);
    } else {
        if (bidx == EMB_BLOCKS && t < HH) g_gsum[t] = 0.f;
        if (t < LL * HH) {
            int l = t >> 6, k = t & 63;
            const float* wr = fW2 + l * HH * HH + k * HH;
            float s = 0.f;
#pragma unroll
            for (int j = 0; j < HH; j++) s += wr[j];
            w2s[t] = s;
        } else if (t < LL * HH + LL) {
            int l = t - LL * HH;
            float s = 0.f;
            for (int j = 0; j < HH; j++) s += fb2[l * HH + j];
            b2s[l] = s;
        }
        __syncthreads();
        int idx = (bidx - EMB_BLOCKS) * 256 + t;
        if (idx < LL * (KLUT + 1)) {
            int l = idx / (KLUT + 1), i = idx % (KLUT + 1);
            float s = -1.f + 2.f * (float)i / (float)KLUT;
            float acc = b2s[l];
            const float* a = fW1 + l * HH;
            const float* bb = fb1 + l * HH;
#pragma unroll 8
            for (int k = 0; k < HH; k++) acc += tanhf(s * a[k] + bb[k]) * w2s[l * HH + k];
            g_lut[idx] = acc;
        }
    }
}

// ---------------- histogram (vectorized) ----------------
__global__ void k_hist(const int* __restrict__ row) {
    int e4 = blockIdx.x * blockDim.x + threadIdx.x;
    if (e4 < EE / 4) {
        int4 r = ((const int4*)row)[e4];
        atomicAdd(&g_deg[r.x], 1); atomicAdd(&g_deg[r.y], 1);
        atomicAdd(&g_deg[r.z], 1); atomicAdd(&g_deg[r.w], 1);
    }
}

// ---------------- scan: per-1024 block sums ----------------
__global__ void k_scan_a() {
    __shared__ int s[256];
    int b = blockIdx.x, acc = 0;
    for (int i = threadIdx.x; i < 1024; i += 256) {
        int g = b * 1024 + i;
        if (g < NN) acc += g_deg[g];
    }
    s[threadIdx.x] = acc; __syncthreads();
    for (int off = 128; off > 0; off >>= 1) {
        if (threadIdx.x < off) s[threadIdx.x] += s[threadIdx.x + off];
        __syncthreads();
    }
    if (threadIdx.x == 0) g_bsums[b] = s[0];
}

// ---------------- scan: final (inlines the block-sum prefix) ----------------
__global__ void k_scan_c() {
    __shared__ int red[128];
    __shared__ int s[1024];
    int b = blockIdx.x, t = threadIdx.x;
    if (t < 128) red[t] = (t < b) ? g_bsums[t] : 0;   // bsums[>=98] always 0
    __syncthreads();
    for (int off = 64; off > 0; off >>= 1) {
        if (t < off) red[t] += red[t + off];
        __syncthreads();
    }
    int g = b * 1024 + t;
    int v = (g < NN) ? g_deg[g] : 0;
    s[t] = v; __syncthreads();
    for (int off = 1; off < 1024; off <<= 1) {
        int add = (t >= off) ? s[t - off] : 0;
        __syncthreads();
        s[t] += add;
        __syncthreads();
    }
    if (g < NN) {
        int rs = s[t] - v + red[0];
        g_rowstart[g] = rs;
        g_cursor[g] = rs;
    }
}

// ---------------- permute edges into CSR order with fs inline ----------------
__global__ void k_permute(const int* __restrict__ row, const int* __restrict__ col,
                          const float* __restrict__ dist) {
    __shared__ float slut[LL * (KLUT + 1)];
    for (int i = threadIdx.x; i < LL * (KLUT + 1); i += blockDim.x) slut[i] = g_lut[i];
    __syncthreads();
    for (int e = blockIdx.x * blockDim.x + threadIdx.x; e < EE;
         e += gridDim.x * blockDim.x) {
        float d = dist[e];
        float cut = (d <= CUT) ? 0.5f * (__cosf(d * (float)(M_PI / 5.0)) + 1.f) : 0.f;
        float s = d * (2.f / CUT) - 1.f;
        float xx = (s + 1.f) * (0.5f * (float)KLUT);
        xx = fminf(fmaxf(xx, 0.f), (float)KLUT - 0.001f);
        int i0 = (int)xx;
        float fr = xx - (float)i0;
        float v0a = slut[i0],        v0b = slut[i0 + 1];
        float v1a = slut[1025 + i0], v1b = slut[1025 + i0 + 1];
        float v2a = slut[2050 + i0], v2b = slut[2050 + i0 + 1];
        float f0 = cut * (v0a + fr * (v0b - v0a));
        float f1 = cut * (v1a + fr * (v1b - v1a));
        float f2 = cut * (v2a + fr * (v2b - v2a));
        int r = row[e], c = col[e];
        int pos = atomicAdd(&g_cursor[r], 1);
        g_csr[pos] = make_float4(__int_as_float(c), f0, f1, f2);
    }
}

// ---------------- gather: agg[n] = sum_e fs_e * h_bf16[col_e]  (8 lanes/node) ----
__global__ void k_gather(int layer) {
    int t = blockIdx.x * blockDim.x + threadIdx.x;
    int node = t >> 3, lane = t & 7;
    if (node >= NN) return;
    int start = g_rowstart[node];
    int d = g_deg[node];
    float acc[8] = {0.f, 0.f, 0.f, 0.f, 0.f, 0.f, 0.f, 0.f};
    const uint4* hb = (const uint4*)g_hb;   // row = 64 bf16 = 8 uint4
    for (int i = 0; i < d; i++) {
        float4 ent = g_csr[start + i];
        int c = __float_as_int(ent.x);
        float f = (layer == 0) ? ent.y : (layer == 1) ? ent.z : ent.w;
        uint4 hv = hb[c * 8 + lane];
#define ACC2(u, j0) { unsigned uu = (u); \
        acc[j0]     += f * __uint_as_float(uu << 16); \
        acc[j0 + 1] += f * __uint_as_float(uu & 0xffff0000u); }
        ACC2(hv.x, 0) ACC2(hv.y, 2) ACC2(hv.z, 4) ACC2(hv.w, 6)
#undef ACC2
    }
    g_agg[node * 16 + lane * 2]     = make_float4(acc[0], acc[1], acc[2], acc[3]);
    g_agg[node * 16 + lane * 2 + 1] = make_float4(acc[4], acc[5], acc[6], acc[7]);
}

// ---------------- node update with packed f32x2 FMA + coalesced epilogue ------
// 128 threads: thread (tc = t&63) handles nodes tc and tc+64; half=t>>6 -> 32 j's
__global__ void __launch_bounds__(128) k_nodeup(
    const float* __restrict__ iW1, const float* __restrict__ ib1,
    const float* __restrict__ iW2, const float* __restrict__ ib2,
    const float* __restrict__ gam, const float* __restrict__ bet,
    int l, int domean) {
    __shared__ float sA[128][65];
    __shared__ float4 sred[128];
    int base = blockIdx.x * 128;
    int tid = threadIdx.x;

    // load agg (coalesced float4)
    for (int idx = tid; idx < 128 * 16; idx += 128) {
        int n = idx >> 4, f4 = idx & 15, gn = base + n;
        float4 v = (gn < NN) ? g_agg[gn * 16 + f4] : make_float4(0.f, 0.f, 0.f, 0.f);
        int jc = f4 * 4;
        sA[n][jc] = v.x; sA[n][jc + 1] = v.y; sA[n][jc + 2] = v.z; sA[n][jc + 3] = v.w;
    }
    __syncthreads();

    int tc = tid & 63, half = tid >> 6, jb = half * 32;
    int n0 = tc, n1 = tc + 64;
    u64 a0[16], a1[16];

    // ---- GEMM1 ----
    {
        const ulonglong2* bb = (const ulonglong2*)(ib1 + l * 64 + jb);
#pragma unroll
        for (int q = 0; q < 8; q++) {
            ulonglong2 bv = bb[q];
            a0[2 * q] = bv.x; a0[2 * q + 1] = bv.y;
            a1[2 * q] = bv.x; a1[2 * q + 1] = bv.y;
        }
        const ulonglong2* W1 = (const ulonglong2*)(iW1 + l * 4096 + jb);
#pragma unroll 2
        for (int k = 0; k < 64; k++) {
            u64 x0 = dup2(sA[n0][k]);
            u64 x1 = dup2(sA[n1][k]);
            const ulonglong2* wr = W1 + k * 16;
#pragma unroll
            for (int q = 0; q < 8; q++) {
                ulonglong2 w = wr[q];
                fma2(a0[2 * q], x0, w.x); fma2(a0[2 * q + 1], x0, w.y);
                fma2(a1[2 * q], x1, w.x); fma2(a1[2 * q + 1], x1, w.y);
            }
        }
    }
    __syncthreads();
#pragma unroll
    for (int q = 0; q < 16; q++) {
        float2 v0 = unpk(a0[q]);
        sA[n0][jb + 2 * q] = sp(v0.x); sA[n0][jb + 2 * q + 1] = sp(v0.y);
        float2 v1 = unpk(a1[q]);
        sA[n1][jb + 2 * q] = sp(v1.x); sA[n1][jb + 2 * q + 1] = sp(v1.y);
    }
    __syncthreads();

    // ---- GEMM2 ----
    {
        const ulonglong2* bb = (const ulonglong2*)(ib2 + l * 64 + jb);
#pragma unroll
        for (int q = 0; q < 8; q++) {
            ulonglong2 bv = bb[q];
            a0[2 * q] = bv.x; a0[2 * q + 1] = bv.y;
            a1[2 * q] = bv.x; a1[2 * q + 1] = bv.y;
        }
        const ulonglong2* W2 = (const ulonglong2*)(iW2 + l * 4096 + jb);
#pragma unroll 2
        for (int k = 0; k < 64; k++) {
            u64 x0 = dup2(sA[n0][k]);
            u64 x1 = dup2(sA[n1][k]);
            const ulonglong2* wr = W2 + k * 16;
#pragma unroll
            for (int q = 0; q < 8; q++) {
                ulonglong2 w = wr[q];
                fma2(a0[2 * q], x0, w.x); fma2(a0[2 * q + 1], x0, w.y);
                fma2(a1[2 * q], x1, w.x); fma2(a1[2 * q + 1], x1, w.y);
            }
        }
    }
    __syncthreads();
#pragma unroll
    for (int q = 0; q < 16; q++) {
        float2 v0 = unpk(a0[q]);
        sA[n0][jb + 2 * q] = v0.x; sA[n0][jb + 2 * q + 1] = v0.y;
        float2 v1 = unpk(a1[q]);
        sA[n1][jb + 2 * q] = v1.x; sA[n1][jb + 2 * q + 1] = v1.y;
    }
    __syncthreads();

    // ---- BN + residual, fully coalesced float4 ----
    float4 macc = make_float4(0.f, 0.f, 0.f, 0.f);
    for (int idx = tid; idx < 128 * 16; idx += 128) {
        int n = idx >> 4, f4 = idx & 15, gn = base + n;
        if (gn < NN) {
            int jc = f4 * 4;
            float4 hv = g_h[gn * 16 + f4];
            float4 gv = *(const float4*)(gam + l * 64 + jc);
            float4 bv = *(const float4*)(bet + l * 64 + jc);
            hv.x += sA[n][jc]     * BN_INV * gv.x + bv.x;
            hv.y += sA[n][jc + 1] * BN_INV * gv.y + bv.y;
            hv.z += sA[n][jc + 2] * BN_INV * gv.z + bv.z;
            hv.w += sA[n][jc + 3] * BN_INV * gv.w + bv.w;
            g_h[gn * 16 + f4] = hv;
            if (l < 2) {
                __nv_bfloat162* hb2 = (__nv_bfloat162*)(g_hb + gn * 64 + jc);
                hb2[0] = __nv_bfloat162(__float2bfloat16_rn(hv.x), __float2bfloat16_rn(hv.y));
                hb2[1] = __nv_bfloat162(__float2bfloat16_rn(hv.z), __float2bfloat16_rn(hv.w));
            }
            if (domean) { macc.x += hv.x; macc.y += hv.y; macc.z += hv.z; macc.w += hv.w; }
        }
    }
    if (domean) {
        sred[tid] = macc;
        __syncthreads();
        if (tid < 16) {
            float4 s = sred[tid];
            for (int g = 1; g < 8; g++) {
                float4 v = sred[tid + 16 * g];
                s.x += v.x; s.y += v.y; s.z += v.z; s.w += v.w;
            }
            atomicAdd(&g_gsum[tid * 4 + 0], s.x);
            atomicAdd(&g_gsum[tid * 4 + 1], s.y);
            atomicAdd(&g_gsum[tid * 4 + 2], s.z);
            atomicAdd(&g_gsum[tid * 4 + 3], s.w);
        }
    }
}

// ---------------- final tiny MLP chain -> out[3] ----------------
__global__ void k_final(const float* __restrict__ oW1, const float* __restrict__ ob1,
                        const float* __restrict__ og1, const float* __restrict__ obt1,
                        const float* __restrict__ oW2, const float* __restrict__ ob2,
                        const float* __restrict__ og2, const float* __restrict__ obt2,
                        const float* __restrict__ finW, const float* __restrict__ finb,
                        float* __restrict__ out) {
    __shared__ float sg[64], s1[32], s2[32];
    int t = threadIdx.x;
    if (t < 64) sg[t] = g_gsum[t] * (1.f / (float)NN);
    __syncthreads();
    if (t < 32) {
        float acc = ob1[t];
        for (int k = 0; k < 64; k++) acc += sg[k] * oW1[k * 32 + t];
        s1[t] = sp(acc) * BN_INV * og1[t] + obt1[t];
    }
    __syncthreads();
    if (t < 32) {
        float acc = ob2[t];
        for (int k = 0; k < 32; k++) acc += s1[k] * oW2[k * 32 + t];
        s2[t] = sp(acc) * BN_INV * og2[t] + obt2[t];
    }
    __syncthreads();
    if (t < 3) {
        float acc = finb[t];
        for (int k = 0; k < 32; k++) acc += s2[k] * finW[k * 3 + t];
        out[t] = acc;
    }
}

// ---------------- launch ----------------
extern "C" void kernel_launch(void* const* d_in, const int* in_sizes, int n_in,
                              void* d_out, int out_size) {
    const float* x    = (const float*)d_in[0];
    const int*   ei   = (const int*)d_in[1];
    const float* dist = (const float*)d_in[2];
    const float* embW = (const float*)d_in[4];
    const float* embB = (const float*)d_in[5];
    const float* fW1  = (const float*)d_in[6];
    const float* fb1  = (const float*)d_in[7];
    const float* fW2  = (const float*)d_in[8];
    const float* fb2  = (const float*)d_in[9];
    const float* iW1  = (const float*)d_in[10];
    const float* ib1  = (const float*)d_in[11];
    const float* iW2  = (const float*)d_in[12];
    const float* ib2  = (const float*)d_in[13];
    const float* gam  = (const float*)d_in[14];
    const float* bet  = (const float*)d_in[15];
    const float* oW1  = (const float*)d_in[16];
    const float* ob1  = (const float*)d_in[17];
    const float* og1  = (const float*)d_in[18];
    const float* obt1 = (const float*)d_in[19];
    const float* oW2  = (const float*)d_in[20];
    const float* ob2  = (const float*)d_in[21];
    const float* og2  = (const float*)d_in[22];
    const float* obt2 = (const float*)d_in[23];
    const float* finW = (const float*)d_in[24];
    const float* finb = (const float*)d_in[25];
    float* out = (float*)d_out;

    const int* row = ei;        // edge_index[0]
    const int* col = ei + EE;   // edge_index[1]

    // launch 0: setup (embed + zero deg/gsum + LUT)
    k_setup<<<EMB_BLOCKS + LUT_BLOCKS, 256>>>(x, embW, embB, fW1, fb1, fW2, fb2);
    // launch 1: histogram
    k_hist<<<(EE / 4 + 255) / 256, 256>>>(row);
    // launches 2-3: scan
    int nb = (NN + 1023) / 1024;           // 98
    k_scan_a<<<nb, 256>>>();
    k_scan_c<<<nb, 1024>>>();
    // launch 4: CSR permute
    k_permute<<<4096, 256>>>(row, col, dist);

    // launch 5 = k_gather(0): this is the one ncu (-s 5) profiles
    for (int l = 0; l < LL; l++) {
        k_gather<<<(NN * 8 + 255) / 256, 256>>>(l);
        k_nodeup<<<(NN + 127) / 128, 128>>>(iW1, ib1, iW2, ib2, gam, bet, l,
                                            (l == LL - 1) ? 1 : 0);
    }
    k_final<<<1, 64>>>(oW1, ob1, og1, obt1, oW2, ob2, og2, obt2, finW, finb, out);
}

// round 5
// speedup vs baseline: 1.0206x; 1.0206x over previous
#include <cuda_runtime.h>
#include <cuda_bf16.h>
#include <math.h>

// ---------------- problem constants ----------------
#define NN      100000
#define EE      1600000
#define HH      64
#define FINW    16
#define LL      3
#define KLUT    1024
#define CUT     5.0f
#define BN_INV  0.9995003749f   // 1/sqrt(1+1e-3)

#define EMB_BLOCKS 25000        // 25000*256 == NN*HH
#define LUT_BLOCKS 16
#define HIST_BLOCKS 1563        // ceil(EE/4/256)

typedef unsigned long long u64;

// ---------------- device scratch (zero-init at module load) ----------------
__device__ float4 g_h[NN * 16];                        // fp32 master h [N,64]
__device__ __align__(16) __nv_bfloat16 g_hb0[NN * 64]; // bf16 gather ping
__device__ __align__(16) __nv_bfloat16 g_hb1[NN * 64]; // bf16 gather pong
__device__ float2 g_csr0[EE];                          // per-layer CSR {col, fs}
__device__ float2 g_csr1[EE];
__device__ float2 g_csr2[EE];
__device__ int    g_deg[NN];        // must be 0 at call entry (k_final re-zeros)
__device__ int    g_rowstart[NN];
__device__ int    g_cursor[NN];
__device__ int    g_total;          // must be 0 at entry (k_final re-zeros)
__device__ float  g_lut[LL * (KLUT + 1)];
__device__ float  g_gsum[HH];       // must be 0 at entry (k_final re-zeros)

__device__ __forceinline__ float sp(float x) {
    return fmaxf(x, 0.f) + log1pf(__expf(-fabsf(x)));
}
__device__ __forceinline__ u64 dup2(float x) {
    u64 r; asm("mov.b64 %0, {%1, %1};" : "=l"(r) : "f"(x)); return r;
}
__device__ __forceinline__ void fma2(u64 &a, u64 x, u64 w) {
    asm("fma.rn.f32x2 %0, %1, %2, %0;" : "+l"(a) : "l"(x), "l"(w));
}
__device__ __forceinline__ float2 unpk(u64 a) {
    float2 r; asm("mov.b64 {%0, %1}, %2;" : "=f"(r.x), "=f"(r.y) : "l"(a)); return r;
}

// ============ k0: embed + filter-LUT + edge histogram (disjoint arrays) ======
__global__ void k0_setup_hist(const float* __restrict__ x,
                              const float* __restrict__ W,
                              const float* __restrict__ b,
                              const float* __restrict__ fW1,
                              const float* __restrict__ fb1,
                              const float* __restrict__ fW2,
                              const float* __restrict__ fb2,
                              const int* __restrict__ row) {
    int bidx = blockIdx.x, t = threadIdx.x;
    if (bidx < EMB_BLOCKS) {
        // ---- embedding: h = x @ emb_W + emb_b ----
        int idx = bidx * 256 + t;
        int n = idx >> 6, j = idx & 63;
        float acc = b[j];
        const float* xr = x + n * FINW;
#pragma unroll
        for (int k = 0; k < FINW; k++) acc += xr[k] * W[k * HH + j];
        ((float*)g_h)[idx] = acc;
        g_hb0[idx] = __float2bfloat16_rn(acc);   // layer 0 reads hb0
    } else if (bidx < EMB_BLOCKS + LUT_BLOCKS) {
        // ---- collapsed filter-MLP LUT ----
        __shared__ float w2s[LL * HH];
        __shared__ float b2s[LL];
        if (t < LL * HH) {
            int l = t >> 6, k = t & 63;
            const float* wr = fW2 + l * HH * HH + k * HH;
            float s = 0.f;
#pragma unroll
            for (int j = 0; j < HH; j++) s += wr[j];
            w2s[t] = s;
        } else if (t < LL * HH + LL) {
            int l = t - LL * HH;
            float s = 0.f;
            for (int j = 0; j < HH; j++) s += fb2[l * HH + j];
            b2s[l] = s;
        }
        __syncthreads();
        int idx = (bidx - EMB_BLOCKS) * 256 + t;
        if (idx < LL * (KLUT + 1)) {
            int l = idx / (KLUT + 1), i = idx % (KLUT + 1);
            float s = -1.f + 2.f * (float)i / (float)KLUT;
            float acc = b2s[l];
            const float* a = fW1 + l * HH;
            const float* bb = fb1 + l * HH;
#pragma unroll 8
            for (int k = 0; k < HH; k++) acc += tanhf(s * a[k] + bb[k]) * w2s[l * HH + k];
            g_lut[idx] = acc;
        }
    } else {
        // ---- histogram (g_deg pre-zeroed by previous call's k_final) ----
        int e4 = (bidx - EMB_BLOCKS - LUT_BLOCKS) * 256 + t;
        if (e4 < EE / 4) {
            int4 r = ((const int4*)row)[e4];
            atomicAdd(&g_deg[r.x], 1); atomicAdd(&g_deg[r.y], 1);
            atomicAdd(&g_deg[r.z], 1); atomicAdd(&g_deg[r.w], 1);
        }
    }
}

// ============ k1: segment allocation (order-free, warp-aggregated atomic) ====
__global__ void k1_alloc() {
    int idx = blockIdx.x * blockDim.x + threadIdx.x;
    int lane = threadIdx.x & 31;
    int d = (idx < NN) ? g_deg[idx] : 0;
    int s = d;
#pragma unroll
    for (int off = 1; off < 32; off <<= 1) {
        int v = __shfl_up_sync(0xffffffffu, s, off);
        if (lane >= off) s += v;
    }
    int tot = __shfl_sync(0xffffffffu, s, 31);
    int base = 0;
    if (lane == 31) base = atomicAdd(&g_total, tot);
    base = __shfl_sync(0xffffffffu, base, 31);
    int start = base + s - d;
    if (idx < NN) { g_rowstart[idx] = start; g_cursor[idx] = start; }
}

// ============ k2: permute edges into CSR order, fs via LUT ===================
__global__ void k2_permute(const int* __restrict__ row, const int* __restrict__ col,
                           const float* __restrict__ dist) {
    __shared__ float slut[LL * (KLUT + 1)];
    for (int i = threadIdx.x; i < LL * (KLUT + 1); i += blockDim.x) slut[i] = g_lut[i];
    __syncthreads();
    for (int e = blockIdx.x * blockDim.x + threadIdx.x; e < EE;
         e += gridDim.x * blockDim.x) {
        float d = dist[e];
        float cut = (d <= CUT) ? 0.5f * (__cosf(d * (float)(M_PI / 5.0)) + 1.f) : 0.f;
        float s = d * (2.f / CUT) - 1.f;
        float xx = (s + 1.f) * (0.5f * (float)KLUT);
        xx = fminf(fmaxf(xx, 0.f), (float)KLUT - 0.001f);
        int i0 = (int)xx;
        float fr = xx - (float)i0;
        float v0a = slut[i0],        v0b = slut[i0 + 1];
        float v1a = slut[1025 + i0], v1b = slut[1025 + i0 + 1];
        float v2a = slut[2050 + i0], v2b = slut[2050 + i0 + 1];
        float f0 = cut * (v0a + fr * (v0b - v0a));
        float f1 = cut * (v1a + fr * (v1b - v1a));
        float f2 = cut * (v2a + fr * (v2b - v2a));
        int r = row[e], c = col[e];
        float cf = __int_as_float(c);
        int pos = atomicAdd(&g_cursor[r], 1);
        g_csr0[pos] = make_float2(cf, f0);
        g_csr1[pos] = make_float2(cf, f1);
        g_csr2[pos] = make_float2(cf, f2);
    }
}

// ============ k3..k5: fused layer = gather (smem) + MLP + BN + residual ======
// 256 threads, 128 nodes per block. Reads hb_in (immutable this layer),
// writes hb_out for the next layer -> no cross-block race.
__global__ void __launch_bounds__(256) k_layer(
    const float* __restrict__ iW1, const float* __restrict__ ib1,
    const float* __restrict__ iW2, const float* __restrict__ ib2,
    const float* __restrict__ gam, const float* __restrict__ bet,
    const __nv_bfloat16* __restrict__ hb_in, __nv_bfloat16* __restrict__ hb_out,
    int l, int domean) {
    __shared__ float sA[128][65];
    __shared__ float4 sred[256];
    int base = blockIdx.x * 128;
    int tid = threadIdx.x;

    // ---- Phase A: gather. 8 lanes per node, 32 node-slots, 4 rounds ----
    const float2* __restrict__ cs = (l == 0) ? g_csr0 : (l == 1) ? g_csr1 : g_csr2;
    const uint4* __restrict__ hb = (const uint4*)hb_in;  // row = 64 bf16 = 8 uint4
    int lane = tid & 7, slot = tid >> 3;
#pragma unroll
    for (int r = 0; r < 4; r++) {
        int n = r * 32 + slot;
        int gn = base + n;
        float acc[8] = {0.f, 0.f, 0.f, 0.f, 0.f, 0.f, 0.f, 0.f};
        if (gn < NN) {
            int start = g_rowstart[gn];
            int d = g_deg[gn];
            const float2* ce = cs + start;
            for (int i = 0; i < d; i++) {
                float2 ent = __ldg(ce + i);
                int c = __float_as_int(ent.x);
                float f = ent.y;
                uint4 hv = __ldg(hb + c * 8 + lane);
#define ACC2(u, j0) { unsigned uu = (u); \
                acc[j0]     += f * __uint_as_float(uu << 16); \
                acc[j0 + 1] += f * __uint_as_float(uu & 0xffff0000u); }
                ACC2(hv.x, 0) ACC2(hv.y, 2) ACC2(hv.z, 4) ACC2(hv.w, 6)
#undef ACC2
            }
        }
        int jc = lane * 8;
#pragma unroll
        for (int j = 0; j < 8; j++) sA[n][jc + j] = acc[j];
    }
    __syncthreads();

    // ---- Phase B: two 64x64 GEMMs with f32x2 packed FMA ----
    int n = tid & 127, half = tid >> 7, jb = half * 32;
    u64 a[16];

    // GEMM1: softplus(agg @ W1 + b1)
    {
        const ulonglong2* bb = (const ulonglong2*)(ib1 + l * 64 + jb);
#pragma unroll
        for (int q = 0; q < 8; q++) {
            ulonglong2 bv = bb[q];
            a[2 * q] = bv.x; a[2 * q + 1] = bv.y;
        }
        const ulonglong2* W1 = (const ulonglong2*)(iW1 + l * 4096 + jb);
#pragma unroll 4
        for (int k = 0; k < 64; k++) {
            u64 xx = dup2(sA[n][k]);
            const ulonglong2* wr = W1 + k * 16;
#pragma unroll
            for (int q = 0; q < 8; q++) {
                ulonglong2 w = __ldg(wr + q);
                fma2(a[2 * q], xx, w.x); fma2(a[2 * q + 1], xx, w.y);
            }
        }
    }
    __syncthreads();
#pragma unroll
    for (int q = 0; q < 16; q++) {
        float2 v = unpk(a[q]);
        sA[n][jb + 2 * q] = sp(v.x); sA[n][jb + 2 * q + 1] = sp(v.y);
    }
    __syncthreads();

    // GEMM2: (.) @ W2 + b2
    {
        const ulonglong2* bb = (const ulonglong2*)(ib2 + l * 64 + jb);
#pragma unroll
        for (int q = 0; q < 8; q++) {
            ulonglong2 bv = bb[q];
            a[2 * q] = bv.x; a[2 * q + 1] = bv.y;
        }
        const ulonglong2* W2 = (const ulonglong2*)(iW2 + l * 4096 + jb);
#pragma unroll 4
        for (int k = 0; k < 64; k++) {
            u64 xx = dup2(sA[n][k]);
            const ulonglong2* wr = W2 + k * 16;
#pragma unroll
            for (int q = 0; q < 8; q++) {
                ulonglong2 w = __ldg(wr + q);
                fma2(a[2 * q], xx, w.x); fma2(a[2 * q + 1], xx, w.y);
            }
        }
    }
    __syncthreads();
#pragma unroll
    for (int q = 0; q < 16; q++) {
        float2 v = unpk(a[q]);
        sA[n][jb + 2 * q] = v.x; sA[n][jb + 2 * q + 1] = v.y;
    }
    __syncthreads();

    // ---- BN + residual, coalesced float4; optional column-mean ----
    float4 macc = make_float4(0.f, 0.f, 0.f, 0.f);
    for (int idx = tid; idx < 128 * 16; idx += 256) {
        int nn = idx >> 4, f4 = idx & 15, gn = base + nn;
        if (gn < NN) {
            int jc = f4 * 4;
            float4 hv = g_h[gn * 16 + f4];
            float4 gv = *(const float4*)(gam + l * 64 + jc);
            float4 bv = *(const float4*)(bet + l * 64 + jc);
            hv.x += sA[nn][jc]     * BN_INV * gv.x + bv.x;
            hv.y += sA[nn][jc + 1] * BN_INV * gv.y + bv.y;
            hv.z += sA[nn][jc + 2] * BN_INV * gv.z + bv.z;
            hv.w += sA[nn][jc + 3] * BN_INV * gv.w + bv.w;
            g_h[gn * 16 + f4] = hv;
            if (hb_out) {
                __nv_bfloat162* hb2 = (__nv_bfloat162*)(hb_out + gn * 64 + jc);
                hb2[0] = __nv_bfloat162(__float2bfloat16_rn(hv.x), __float2bfloat16_rn(hv.y));
                hb2[1] = __nv_bfloat162(__float2bfloat16_rn(hv.z), __float2bfloat16_rn(hv.w));
            }
            if (domean) { macc.x += hv.x; macc.y += hv.y; macc.z += hv.z; macc.w += hv.w; }
        }
    }
    if (domean) {
        sred[tid] = macc;
        __syncthreads();
        if (tid < 16) {
            float4 s = sred[tid];
#pragma unroll
            for (int g = 1; g < 16; g++) {
                float4 v = sred[tid + 16 * g];
                s.x += v.x; s.y += v.y; s.z += v.z; s.w += v.w;
            }
            atomicAdd(&g_gsum[tid * 4 + 0], s.x);
            atomicAdd(&g_gsum[tid * 4 + 1], s.y);
            atomicAdd(&g_gsum[tid * 4 + 2], s.z);
            atomicAdd(&g_gsum[tid * 4 + 3], s.w);
        }
    }
}

// ============ k6: final MLP chain -> out[3]; re-zero state for next call =====
__global__ void k_final(const float* __restrict__ oW1, const float* __restrict__ ob1,
                        const float* __restrict__ og1, const float* __restrict__ obt1,
                        const float* __restrict__ oW2, const float* __restrict__ ob2,
                        const float* __restrict__ og2, const float* __restrict__ obt2,
                        const float* __restrict__ finW, const float* __restrict__ finb,
                        float* __restrict__ out) {
    __shared__ float sg[64], s1[32], s2[32];
    int t = threadIdx.x;
    if (t < 64) sg[t] = g_gsum[t] * (1.f / (float)NN);
    __syncthreads();
    // re-zero persistent state for the NEXT call (every call does it -> deterministic)
    if (t < 64) g_gsum[t] = 0.f;
    if (t == 0) g_total = 0;
    {
        int4 z = make_int4(0, 0, 0, 0);
        int4* dz = (int4*)g_deg;
        for (int i = t; i < NN / 4; i += blockDim.x) dz[i] = z;
    }
    if (t < 32) {
        float acc = ob1[t];
        for (int k = 0; k < 64; k++) acc += sg[k] * oW1[k * 32 + t];
        s1[t] = sp(acc) * BN_INV * og1[t] + obt1[t];
    }
    __syncthreads();
    if (t < 32) {
        float acc = ob2[t];
        for (int k = 0; k < 32; k++) acc += s1[k] * oW2[k * 32 + t];
        s2[t] = sp(acc) * BN_INV * og2[t] + obt2[t];
    }
    __syncthreads();
    if (t < 3) {
        float acc = finb[t];
        for (int k = 0; k < 32; k++) acc += s2[k] * finW[k * 3 + t];
        out[t] = acc;
    }
}

// ---------------- launch ----------------
extern "C" void kernel_launch(void* const* d_in, const int* in_sizes, int n_in,
                              void* d_out, int out_size) {
    const float* x    = (const float*)d_in[0];
    const int*   ei   = (const int*)d_in[1];
    const float* dist = (const float*)d_in[2];
    const float* embW = (const float*)d_in[4];
    const float* embB = (const float*)d_in[5];
    const float* fW1  = (const float*)d_in[6];
    const float* fb1  = (const float*)d_in[7];
    const float* fW2  = (const float*)d_in[8];
    const float* fb2  = (const float*)d_in[9];
    const float* iW1  = (const float*)d_in[10];
    const float* ib1  = (const float*)d_in[11];
    const float* iW2  = (const float*)d_in[12];
    const float* ib2  = (const float*)d_in[13];
    const float* gam  = (const float*)d_in[14];
    const float* bet  = (const float*)d_in[15];
    const float* oW1  = (const float*)d_in[16];
    const float* ob1  = (const float*)d_in[17];
    const float* og1  = (const float*)d_in[18];
    const float* obt1 = (const float*)d_in[19];
    const float* oW2  = (const float*)d_in[20];
    const float* ob2  = (const float*)d_in[21];
    const float* og2  = (const float*)d_in[22];
    const float* obt2 = (const float*)d_in[23];
    const float* finW = (const float*)d_in[24];
    const float* finb = (const float*)d_in[25];
    float* out = (float*)d_out;

    const int* row = ei;        // edge_index[0]
    const int* col = ei + EE;   // edge_index[1]

    __nv_bfloat16 *hb0, *hb1;
    cudaGetSymbolAddress((void**)&hb0, g_hb0);
    cudaGetSymbolAddress((void**)&hb1, g_hb1);

    // kernel-index 0
    k0_setup_hist<<<EMB_BLOCKS + LUT_BLOCKS + HIST_BLOCKS, 256>>>(
        x, embW, embB, fW1, fb1, fW2, fb2, row);
    // kernel-index 1
    k1_alloc<<<(NN + 255) / 256, 256>>>();
    // kernel-index 2
    k2_permute<<<2048, 256>>>(row, col, dist);
    // kernel-index 3..5  (index 3 = the one ncu captures)
    // layer l reads hb[l&1], writes hb[(l+1)&1]; last layer writes nothing.
    k_layer<<<(NN + 127) / 128, 256>>>(iW1, ib1, iW2, ib2, gam, bet,
                                       hb0, hb1, 0, 0);
    k_layer<<<(NN + 127) / 128, 256>>>(iW1, ib1, iW2, ib2, gam, bet,
                                       hb1, hb0, 1, 0);
    k_layer<<<(NN + 127) / 128, 256>>>(iW1, ib1, iW2, ib2, gam, bet,
                                       hb0, (__nv_bfloat16*)nullptr, 2, 1);
    // kernel-index 6
    k_final<<<1, 1024>>>(oW1, ob1, og1, obt1, oW2, ob2, og2, obt2, finW, finb, out);
}

// round 6
// speedup vs baseline: 1.7467x; 1.7114x over previous
#include <cuda_runtime.h>
#include <cuda_bf16.h>
#include <math.h>

// ---------------- problem constants ----------------
#define NN      100000
#define EE      1600000
#define HH      64
#define FINW    16
#define LL      3
#define KLUT    1024
#define CUT     5.0f
#define BN_INV  0.9995003749f   // 1/sqrt(1+1e-3)

#define EMB_BLOCKS 25000        // 25000*256 == NN*HH
#define LUT_BLOCKS 16
#define HIST_BLOCKS 1563        // ceil(EE/4/256)

typedef unsigned long long u64;

// ---------------- device scratch (zero-init at module load) ----------------
__device__ float4 g_h[NN * 16];                        // fp32 master h [N,64]
__device__ __align__(16) __nv_bfloat16 g_hb0[NN * 64]; // bf16 gather ping
__device__ __align__(16) __nv_bfloat16 g_hb1[NN * 64]; // bf16 gather pong
__device__ float4 g_csr[EE];                           // {col, fs0, fs1, fs2}
__device__ int    g_deg[NN];        // 0 at call entry (k_final re-zeros)
__device__ int    g_rowstart[NN];
__device__ int    g_cursor[NN];
__device__ int    g_total;          // 0 at entry (k_final re-zeros)
__device__ float  g_lut[LL * (KLUT + 1)];
__device__ float  g_gsum[HH];       // 0 at entry (k_final re-zeros)

__device__ __forceinline__ float sp(float x) {
    return fmaxf(x, 0.f) + log1pf(__expf(-fabsf(x)));
}
__device__ __forceinline__ u64 dup2(float x) {
    u64 r; asm("mov.b64 %0, {%1, %1};" : "=l"(r) : "f"(x)); return r;
}
__device__ __forceinline__ void fma2(u64 &a, u64 x, u64 w) {
    asm("fma.rn.f32x2 %0, %1, %2, %0;" : "+l"(a) : "l"(x), "l"(w));
}
__device__ __forceinline__ float2 unpk(u64 a) {
    float2 r; asm("mov.b64 {%0, %1}, %2;" : "=f"(r.x), "=f"(r.y) : "l"(a)); return r;
}

// ============ k0: embed + filter-LUT + edge histogram (disjoint arrays) ======
__global__ void k0_setup_hist(const float* __restrict__ x,
                              const float* __restrict__ W,
                              const float* __restrict__ b,
                              const float* __restrict__ fW1,
                              const float* __restrict__ fb1,
                              const float* __restrict__ fW2,
                              const float* __restrict__ fb2,
                              const int* __restrict__ row) {
    int bidx = blockIdx.x, t = threadIdx.x;
    if (bidx < EMB_BLOCKS) {
        int idx = bidx * 256 + t;
        int n = idx >> 6, j = idx & 63;
        float acc = b[j];
        const float* xr = x + n * FINW;
#pragma unroll
        for (int k = 0; k < FINW; k++) acc += xr[k] * W[k * HH + j];
        ((float*)g_h)[idx] = acc;
        g_hb0[idx] = __float2bfloat16_rn(acc);   // layer 0 reads hb0
    } else if (bidx < EMB_BLOCKS + LUT_BLOCKS) {
        __shared__ float w2s[LL * HH];
        __shared__ float b2s[LL];
        if (t < LL * HH) {
            int l = t >> 6, k = t & 63;
            const float* wr = fW2 + l * HH * HH + k * HH;
            float s = 0.f;
#pragma unroll
            for (int j = 0; j < HH; j++) s += wr[j];
            w2s[t] = s;
        } else if (t < LL * HH + LL) {
            int l = t - LL * HH;
            float s = 0.f;
            for (int j = 0; j < HH; j++) s += fb2[l * HH + j];
            b2s[l] = s;
        }
        __syncthreads();
        int idx = (bidx - EMB_BLOCKS) * 256 + t;
        if (idx < LL * (KLUT + 1)) {
            int l = idx / (KLUT + 1), i = idx % (KLUT + 1);
            float s = -1.f + 2.f * (float)i / (float)KLUT;
            float acc = b2s[l];
            const float* a = fW1 + l * HH;
            const float* bb = fb1 + l * HH;
#pragma unroll 8
            for (int k = 0; k < HH; k++) acc += tanhf(s * a[k] + bb[k]) * w2s[l * HH + k];
            g_lut[idx] = acc;
        }
    } else {
        int e4 = (bidx - EMB_BLOCKS - LUT_BLOCKS) * 256 + t;
        if (e4 < EE / 4) {
            int4 r = ((const int4*)row)[e4];
            atomicAdd(&g_deg[r.x], 1); atomicAdd(&g_deg[r.y], 1);
            atomicAdd(&g_deg[r.z], 1); atomicAdd(&g_deg[r.w], 1);
        }
    }
}

// ============ k1: segment allocation (order-free, warp-aggregated atomic) ====
__global__ void k1_alloc() {
    int idx = blockIdx.x * blockDim.x + threadIdx.x;
    int lane = threadIdx.x & 31;
    int d = (idx < NN) ? g_deg[idx] : 0;
    int s = d;
#pragma unroll
    for (int off = 1; off < 32; off <<= 1) {
        int v = __shfl_up_sync(0xffffffffu, s, off);
        if (lane >= off) s += v;
    }
    int tot = __shfl_sync(0xffffffffu, s, 31);
    int base = 0;
    if (lane == 31) base = atomicAdd(&g_total, tot);
    base = __shfl_sync(0xffffffffu, base, 31);
    int start = base + s - d;
    if (idx < NN) { g_rowstart[idx] = start; g_cursor[idx] = start; }
}

// ============ k2: permute edges into CSR order, fs via LUT ===================
__global__ void k2_permute(const int* __restrict__ row, const int* __restrict__ col,
                           const float* __restrict__ dist) {
    __shared__ float slut[LL * (KLUT + 1)];
    for (int i = threadIdx.x; i < LL * (KLUT + 1); i += blockDim.x) slut[i] = g_lut[i];
    __syncthreads();
    for (int e = blockIdx.x * blockDim.x + threadIdx.x; e < EE;
         e += gridDim.x * blockDim.x) {
        float d = dist[e];
        float cut = (d <= CUT) ? 0.5f * (__cosf(d * (float)(M_PI / 5.0)) + 1.f) : 0.f;
        float s = d * (2.f / CUT) - 1.f;
        float xx = (s + 1.f) * (0.5f * (float)KLUT);
        xx = fminf(fmaxf(xx, 0.f), (float)KLUT - 0.001f);
        int i0 = (int)xx;
        float fr = xx - (float)i0;
        float v0a = slut[i0],        v0b = slut[i0 + 1];
        float v1a = slut[1025 + i0], v1b = slut[1025 + i0 + 1];
        float v2a = slut[2050 + i0], v2b = slut[2050 + i0 + 1];
        float f0 = cut * (v0a + fr * (v0b - v0a));
        float f1 = cut * (v1a + fr * (v1b - v1a));
        float f2 = cut * (v2a + fr * (v2b - v2a));
        int r = row[e], c = col[e];
        int pos = atomicAdd(&g_cursor[r], 1);
        g_csr[pos] = make_float4(__int_as_float(c), f0, f1, f2);
    }
}

// ============ k3..k5: fused layer ============================================
// 512 threads, 128 nodes/block. Gather: 8 lanes/node, lane-cooperative batches
// of 8 edges (coalesced CSR + shfl broadcast -> MLP~8). GEMM: W1/W2 staged in
// smem (kills the per-thread global-LDG LSU floor), 8 f32x2 accums/thread.
__global__ void __launch_bounds__(512, 2) k_layer(
    const float* __restrict__ iW1, const float* __restrict__ ib1,
    const float* __restrict__ iW2, const float* __restrict__ ib2,
    const float* __restrict__ gam, const float* __restrict__ bet,
    const __nv_bfloat16* __restrict__ hb_in, __nv_bfloat16* __restrict__ hb_out,
    int l, int domean) {
    __shared__ float sA[128][65];
    __shared__ float sW1[64 * 64];
    __shared__ float sW2[64 * 64];
    __shared__ float4 sred[512];
    int base = blockIdx.x * 128;
    int tid = threadIdx.x;

    // ---- stage weights into smem (visible after the gather __syncthreads) ----
    {
        const float4* w1g = (const float4*)(iW1 + l * 4096);
        const float4* w2g = (const float4*)(iW2 + l * 4096);
        for (int i = tid; i < 1024; i += 512) {
            ((float4*)sW1)[i] = __ldg(w1g + i);
            ((float4*)sW2)[i] = __ldg(w2g + i);
        }
    }

    // ---- Phase A: gather (2 rounds of 64 node-slots) ----
    const uint4* __restrict__ hb = (const uint4*)hb_in;  // row = 64 bf16 = 8 uint4
    int lane = tid & 7, slot = tid >> 3;
    unsigned gmask = 0xFFu << ((tid & 31) & ~7);
#pragma unroll
    for (int r = 0; r < 2; r++) {
        int n = r * 64 + slot;
        int gn = base + n;
        float acc[8] = {0.f, 0.f, 0.f, 0.f, 0.f, 0.f, 0.f, 0.f};
        if (gn < NN) {
            int start = g_rowstart[gn];
            int d = g_deg[gn];
            const float4* ce = g_csr + start;
            for (int i0 = 0; i0 < d; i0 += 8) {
                int ii = i0 + lane;
                float4 ent = (ii < d) ? __ldg(ce + ii)
                                      : make_float4(__int_as_float(0), 0.f, 0.f, 0.f);
                float fv = (l == 0) ? ent.y : (l == 1) ? ent.z : ent.w;
                int cv = __float_as_int(ent.x);
#pragma unroll
                for (int j = 0; j < 8; j++) {
                    float f = __shfl_sync(gmask, fv, j, 8);
                    int c = __shfl_sync(gmask, cv, j, 8);
                    uint4 hv = __ldg(hb + c * 8 + lane);
#define ACC2(u, j0) { unsigned uu = (u); \
                    acc[j0]     += f * __uint_as_float(uu << 16); \
                    acc[j0 + 1] += f * __uint_as_float(uu & 0xffff0000u); }
                    ACC2(hv.x, 0) ACC2(hv.y, 2) ACC2(hv.z, 4) ACC2(hv.w, 6)
#undef ACC2
                }
            }
        }
        int jc = lane * 8;
#pragma unroll
        for (int j = 0; j < 8; j++) sA[n][jc + j] = acc[j];
    }
    __syncthreads();

    // ---- Phase B: two 64x64 GEMMs from smem weights ----
    // thread: node n = tid&127, quarter q4 = tid>>7 -> 16 output columns
    int n = tid & 127, q4 = tid >> 7, jb = q4 * 16;
    u64 a[8];

    // GEMM1: softplus(agg @ W1 + b1)
    {
        const ulonglong2* bb = (const ulonglong2*)(ib1 + l * 64 + jb);
#pragma unroll
        for (int q = 0; q < 4; q++) {
            ulonglong2 bv = __ldg(bb + q);
            a[2 * q] = bv.x; a[2 * q + 1] = bv.y;
        }
#pragma unroll 4
        for (int k = 0; k < 64; k++) {
            u64 xx = dup2(sA[n][k]);
            const ulonglong2* wr = (const ulonglong2*)(sW1 + k * 64 + jb);
#pragma unroll
            for (int q = 0; q < 4; q++) {
                ulonglong2 w = wr[q];
                fma2(a[2 * q], xx, w.x); fma2(a[2 * q + 1], xx, w.y);
            }
        }
    }
    __syncthreads();
#pragma unroll
    for (int q = 0; q < 8; q++) {
        float2 v = unpk(a[q]);
        sA[n][jb + 2 * q] = sp(v.x); sA[n][jb + 2 * q + 1] = sp(v.y);
    }
    __syncthreads();

    // GEMM2: (.) @ W2 + b2
    {
        const ulonglong2* bb = (const ulonglong2*)(ib2 + l * 64 + jb);
#pragma unroll
        for (int q = 0; q < 4; q++) {
            ulonglong2 bv = __ldg(bb + q);
            a[2 * q] = bv.x; a[2 * q + 1] = bv.y;
        }
#pragma unroll 4
        for (int k = 0; k < 64; k++) {
            u64 xx = dup2(sA[n][k]);
            const ulonglong2* wr = (const ulonglong2*)(sW2 + k * 64 + jb);
#pragma unroll
            for (int q = 0; q < 4; q++) {
                ulonglong2 w = wr[q];
                fma2(a[2 * q], xx, w.x); fma2(a[2 * q + 1], xx, w.y);
            }
        }
    }
    __syncthreads();
#pragma unroll
    for (int q = 0; q < 8; q++) {
        float2 v = unpk(a[q]);
        sA[n][jb + 2 * q] = v.x; sA[n][jb + 2 * q + 1] = v.y;
    }
    __syncthreads();

    // ---- BN + residual, coalesced float4; optional column-mean ----
    float4 macc = make_float4(0.f, 0.f, 0.f, 0.f);
    for (int idx = tid; idx < 128 * 16; idx += 512) {
        int nn = idx >> 4, f4 = idx & 15, gn = base + nn;
        if (gn < NN) {
            int jc = f4 * 4;
            float4 hv = g_h[gn * 16 + f4];
            float4 gv = *(const float4*)(gam + l * 64 + jc);
            float4 bv = *(const float4*)(bet + l * 64 + jc);
            hv.x += sA[nn][jc]     * BN_INV * gv.x + bv.x;
            hv.y += sA[nn][jc + 1] * BN_INV * gv.y + bv.y;
            hv.z += sA[nn][jc + 2] * BN_INV * gv.z + bv.z;
            hv.w += sA[nn][jc + 3] * BN_INV * gv.w + bv.w;
            g_h[gn * 16 + f4] = hv;
            if (hb_out) {
                __nv_bfloat162* hb2 = (__nv_bfloat162*)(hb_out + gn * 64 + jc);
                hb2[0] = __nv_bfloat162(__float2bfloat16_rn(hv.x), __float2bfloat16_rn(hv.y));
                hb2[1] = __nv_bfloat162(__float2bfloat16_rn(hv.z), __float2bfloat16_rn(hv.w));
            }
            if (domean) { macc.x += hv.x; macc.y += hv.y; macc.z += hv.z; macc.w += hv.w; }
        }
    }
    if (domean) {
        sred[tid] = macc;
        __syncthreads();
#pragma unroll
        for (int off = 256; off >= 16; off >>= 1) {
            if (tid < off) {
                float4 o = sred[tid + off];
                float4 s = sred[tid];
                s.x += o.x; s.y += o.y; s.z += o.z; s.w += o.w;
                sred[tid] = s;
            }
            __syncthreads();
        }
        if (tid < 16) {
            float4 s = sred[tid];
            atomicAdd(&g_gsum[tid * 4 + 0], s.x);
            atomicAdd(&g_gsum[tid * 4 + 1], s.y);
            atomicAdd(&g_gsum[tid * 4 + 2], s.z);
            atomicAdd(&g_gsum[tid * 4 + 3], s.w);
        }
    }
}

// ============ k6: final MLP chain -> out[3]; re-zero state for next call =====
__global__ void k_final(const float* __restrict__ oW1, const float* __restrict__ ob1,
                        const float* __restrict__ og1, const float* __restrict__ obt1,
                        const float* __restrict__ oW2, const float* __restrict__ ob2,
                        const float* __restrict__ og2, const float* __restrict__ obt2,
                        const float* __restrict__ finW, const float* __restrict__ finb,
                        float* __restrict__ out) {
    __shared__ float sg[64], s1[32], s2[32];
    int t = threadIdx.x;
    if (t < 64) sg[t] = g_gsum[t] * (1.f / (float)NN);
    __syncthreads();
    if (t < 64) g_gsum[t] = 0.f;
    if (t == 0) g_total = 0;
    {
        int4 z = make_int4(0, 0, 0, 0);
        int4* dz = (int4*)g_deg;
        for (int i = t; i < NN / 4; i += blockDim.x) dz[i] = z;
    }
    if (t < 32) {
        float acc = ob1[t];
        for (int k = 0; k < 64; k++) acc += sg[k] * oW1[k * 32 + t];
        s1[t] = sp(acc) * BN_INV * og1[t] + obt1[t];
    }
    __syncthreads();
    if (t < 32) {
        float acc = ob2[t];
        for (int k = 0; k < 32; k++) acc += s1[k] * oW2[k * 32 + t];
        s2[t] = sp(acc) * BN_INV * og2[t] + obt2[t];
    }
    __syncthreads();
    if (t < 3) {
        float acc = finb[t];
        for (int k = 0; k < 32; k++) acc += s2[k] * finW[k * 3 + t];
        out[t] = acc;
    }
}

// ---------------- launch ----------------
extern "C" void kernel_launch(void* const* d_in, const int* in_sizes, int n_in,
                              void* d_out, int out_size) {
    const float* x    = (const float*)d_in[0];
    const int*   ei   = (const int*)d_in[1];
    const float* dist = (const float*)d_in[2];
    const float* embW = (const float*)d_in[4];
    const float* embB = (const float*)d_in[5];
    const float* fW1  = (const float*)d_in[6];
    const float* fb1  = (const float*)d_in[7];
    const float* fW2  = (const float*)d_in[8];
    const float* fb2  = (const float*)d_in[9];
    const float* iW1  = (const float*)d_in[10];
    const float* ib1  = (const float*)d_in[11];
    const float* iW2  = (const float*)d_in[12];
    const float* ib2  = (const float*)d_in[13];
    const float* gam  = (const float*)d_in[14];
    const float* bet  = (const float*)d_in[15];
    const float* oW1  = (const float*)d_in[16];
    const float* ob1  = (const float*)d_in[17];
    const float* og1  = (const float*)d_in[18];
    const float* obt1 = (const float*)d_in[19];
    const float* oW2  = (const float*)d_in[20];
    const float* ob2  = (const float*)d_in[21];
    const float* og2  = (const float*)d_in[22];
    const float* obt2 = (const float*)d_in[23];
    const float* finW = (const float*)d_in[24];
    const float* finb = (const float*)d_in[25];
    float* out = (float*)d_out;

    const int* row = ei;        // edge_index[0]
    const int* col = ei + EE;   // edge_index[1]

    __nv_bfloat16 *hb0, *hb1;
    cudaGetSymbolAddress((void**)&hb0, g_hb0);
    cudaGetSymbolAddress((void**)&hb1, g_hb1);

    // kernel-index 0
    k0_setup_hist<<<EMB_BLOCKS + LUT_BLOCKS + HIST_BLOCKS, 256>>>(
        x, embW, embB, fW1, fb1, fW2, fb2, row);
    // kernel-index 1
    k1_alloc<<<(NN + 255) / 256, 256>>>();
    // kernel-index 2
    k2_permute<<<2048, 256>>>(row, col, dist);
    // kernel-index 3..5  (index 3 = the one ncu captures)
    k_layer<<<(NN + 127) / 128, 512>>>(iW1, ib1, iW2, ib2, gam, bet,
                                       hb0, hb1, 0, 0);
    k_layer<<<(NN + 127) / 128, 512>>>(iW1, ib1, iW2, ib2, gam, bet,
                                       hb1, hb0, 1, 0);
    k_layer<<<(NN + 127) / 128, 512>>>(iW1, ib1, iW2, ib2, gam, bet,
                                       hb0, (__nv_bfloat16*)nullptr, 2, 1);
    // kernel-index 6
    k_final<<<1, 1024>>>(oW1, ob1, og1, obt1, oW2, ob2, og2, obt2, finW, finb, out);
}